// round 7
// baseline (speedup 1.0000x reference)
#include <cuda_runtime.h>
#include <cuda_bf16.h>
#include <math.h>

// Problem constants (fixed by setup_inputs):
// B=16, nW=64, BnW=1024, N=64, C=256, H=8, d=32, rows R=65536
// Output layout (7 concatenated f32 tensors):
//   out  [0, SEG)            qm [SEG,2SEG)  km [2SEG,3SEG)  vm [3SEG,4SEG)
//   cell [4SEG, 4SEG+2SEG)   am [6SEG,7SEG) om [7SEG,8SEG)
static const size_t SEG    = 16777216ull;
static const size_t O_QM   = 1ull * SEG;
static const size_t O_KM   = 2ull * SEG;
static const size_t O_VM   = 3ull * SEG;
static const size_t O_CELL = 4ull * SEG;
static const size_t O_AM   = 6ull * SEG;
static const size_t O_OM   = 7ull * SEG;

// ---------------- static device scratch (no allocations) ----------------
__device__ float    g_y[50331648];     // pre-BN q|k|v activations (65536 x 768)
__device__ float    g_yo[16777216];    // pre-BN o activations (65536 x 256)
__device__ float    g_out2[16777216];  // attn-LIF spikes (input of O GEMM)
__device__ float    g_cs[524288];      // (BnW, N, H) coincidence state
__device__ float    g_bias[32768];     // (H, N, N) relative position bias
__device__ unsigned g_qbits[524288];   // (BnW, H, N): packed spikes over d=32
__device__ unsigned g_kbits[524288];
__device__ unsigned g_vbits[524288];
__device__ double   g_part[393216];    // stats partials: 256 blocks x (sum,sumsq) x 768
__device__ float    g_scale[768], g_shift[768];   // folded BN scale/shift (q|k|v)
__device__ float    g_scale_o[256], g_shift_o[256];

// ---------------- cs = mean over last axis of cell_mem ----------------
__global__ void k_cs(const float* __restrict__ cell) {
    const int b = blockIdx.x;          // 0..1023
    const int t = threadIdx.x;         // 0..511
    const int h = t >> 6, n = t & 63;
    const float4* p = (const float4*)(cell + (((size_t)b * 8 + h) * 64 + n) * 64);
    float s = 0.f;
#pragma unroll
    for (int i = 0; i < 16; ++i) { float4 v = p[i]; s += (v.x + v.y) + (v.z + v.w); }
    g_cs[b * 512 + n * 8 + h] = s * (1.0f / 64.0f);
}

// ---------------- relative-position bias gather: bias[h][n][m] ----------------
__global__ void k_bias(const float* __restrict__ rel_table, const int* __restrict__ rel_index) {
    const int i = blockIdx.x * 256 + threadIdx.x;   // < 32768
    const int h = i >> 12, nm = i & 4095;
    g_bias[i] = rel_table[rel_index[nm] * 8 + h];
}

// ---------------- SGEMM: Y[m, colOff+c] = sum_k A[m,k] * W[c,k], K=256 ----------
// 128x128 tile, BK=8, 256 threads, 8x8 microtile, double-buffered smem.
// sel=0: A=Aext (x), Y=g_y.  sel=1: A=g_out2, Y=g_yo.
__global__ __launch_bounds__(256) void sgemm(
    const float* __restrict__ Aext, const float* __restrict__ W,
    int sel, int ldY, int colOff)
{
    const float* A = sel ? g_out2 : Aext;
    float*       Y = sel ? g_yo   : g_y;

    __shared__ __align__(16) float As[2][8][128];
    __shared__ __align__(16) float Bs[2][8][128];

    const int tid  = threadIdx.x;
    const int m0   = blockIdx.x << 7;
    const int c0   = blockIdx.y << 7;
    const int lrow = tid >> 1;          // 0..127
    const int lk4  = (tid & 1) << 2;    // 0 or 4

    const float* Ap = A + (size_t)(m0 + lrow) * 256 + lk4;
    const float* Wp = W + (size_t)(c0 + lrow) * 256 + lk4;

    {
        float4 a = *(const float4*)Ap;
        float4 w = *(const float4*)Wp;
        As[0][lk4 + 0][lrow] = a.x; As[0][lk4 + 1][lrow] = a.y;
        As[0][lk4 + 2][lrow] = a.z; As[0][lk4 + 3][lrow] = a.w;
        Bs[0][lk4 + 0][lrow] = w.x; Bs[0][lk4 + 1][lrow] = w.y;
        Bs[0][lk4 + 2][lrow] = w.z; Bs[0][lk4 + 3][lrow] = w.w;
    }
    __syncthreads();

    const int mb = (tid >> 4) << 3;   // 0..120
    const int nb = (tid & 15) << 3;   // 0..120

    float acc[8][8];
#pragma unroll
    for (int i = 0; i < 8; ++i)
#pragma unroll
        for (int j = 0; j < 8; ++j) acc[i][j] = 0.f;

    int buf = 0;
    for (int kt = 0; kt < 32; ++kt) {
        float4 an, wn;
        if (kt < 31) {
            an = *(const float4*)(Ap + (kt + 1) * 8);
            wn = *(const float4*)(Wp + (kt + 1) * 8);
        }
#pragma unroll
        for (int kk = 0; kk < 8; ++kk) {
            float ar[8], br[8];
            *(float4*)(ar)     = *(const float4*)&As[buf][kk][mb];
            *(float4*)(ar + 4) = *(const float4*)&As[buf][kk][mb + 4];
            *(float4*)(br)     = *(const float4*)&Bs[buf][kk][nb];
            *(float4*)(br + 4) = *(const float4*)&Bs[buf][kk][nb + 4];
#pragma unroll
            for (int i = 0; i < 8; ++i)
#pragma unroll
                for (int j = 0; j < 8; ++j)
                    acc[i][j] = fmaf(ar[i], br[j], acc[i][j]);
        }
        if (kt < 31) {
            const int nbuf = buf ^ 1;
            As[nbuf][lk4 + 0][lrow] = an.x; As[nbuf][lk4 + 1][lrow] = an.y;
            As[nbuf][lk4 + 2][lrow] = an.z; As[nbuf][lk4 + 3][lrow] = an.w;
            Bs[nbuf][lk4 + 0][lrow] = wn.x; Bs[nbuf][lk4 + 1][lrow] = wn.y;
            Bs[nbuf][lk4 + 2][lrow] = wn.z; Bs[nbuf][lk4 + 3][lrow] = wn.w;
            __syncthreads();
        }
        buf ^= 1;
    }

#pragma unroll
    for (int i = 0; i < 8; ++i) {
        size_t r = (size_t)(m0 + mb + i) * ldY + colOff + c0 + nb;
        *(float4*)&Y[r]     = make_float4(acc[i][0], acc[i][1], acc[i][2], acc[i][3]);
        *(float4*)&Y[r + 4] = make_float4(acc[i][4], acc[i][5], acc[i][6], acc[i][7]);
    }
}

// ---------------- BN stats, stage 1: per-rowblock sum/sumsq (fp64, fixed order) ---
__global__ void k_stats_partial(int sel, int ldY) {
    const float* Y = sel ? g_yo : g_y;
    const int c = threadIdx.x;                       // 0..cols-1 (blockDim = cols)
    const float* p = Y + (size_t)blockIdx.x * 256 * ldY + c;
    double s = 0.0, s2 = 0.0;
    for (int r = 0; r < 256; ++r) {
        double v = (double)p[(size_t)r * ldY];
        s += v;
        s2 = fma(v, v, s2);
    }
    g_part[(size_t)blockIdx.x * 1536 + c]       = s;
    g_part[(size_t)blockIdx.x * 1536 + 768 + c] = s2;
}

// ---------------- BN stats, stage 2: fold into scale/shift ----------------
__global__ void k_stats_final(const float* __restrict__ gamma, const float* __restrict__ beta,
                              int colOff, int sel) {
    const int c = threadIdx.x;                       // 256 threads
    double s = 0.0, s2 = 0.0;
    for (int b = 0; b < 256; ++b) {
        s  += g_part[(size_t)b * 1536 + colOff + c];
        s2 += g_part[(size_t)b * 1536 + 768 + colOff + c];
    }
    const double mean = s * (1.0 / 65536.0);
    const double var  = s2 * (1.0 / 65536.0) - mean * mean;
    const double rs   = 1.0 / sqrt(var + 1e-5);
    const double g    = (double)gamma[c];
    float* sc = sel ? g_scale_o : g_scale;
    float* sh = sel ? g_shift_o : g_shift;
    sc[colOff + c] = (float)(g * rs);
    sh[colOff + c] = (float)((double)beta[c] - g * rs * mean);
}

// ---------------- Q/K/V epilogue: BN + feedback + LIF + bit-pack ----------------
__global__ __launch_bounds__(256) void k_qkv_epi(
    const float* __restrict__ qmem, const float* __restrict__ kmem,
    const float* __restrict__ vmem,
    const float* __restrict__ Wfb, const float* __restrict__ bfb,
    const float* __restrict__ betas, float* __restrict__ ob)
{
    const int c    = threadIdx.x;       // channel 0..255
    const int lane = c & 31;            // = d
    const int h    = c >> 5;            // head
    float wf[8];
#pragma unroll
    for (int j = 0; j < 8; ++j) wf[j] = Wfb[c * 8 + j];
    const float bfbc = bfb[c];
    const float b0 = betas[0], b1 = betas[1], b2 = betas[2];
    const float sq = g_scale[c],       hq = g_shift[c];
    const float sk = g_scale[256 + c], hk = g_shift[256 + c];
    const float sv = g_scale[512 + c], hv = g_shift[512 + c];

    const int r0 = blockIdx.x * 16;
    for (int rr = 0; rr < 16; ++rr) {
        const int r = r0 + rr;
        const int b = r >> 6, n = r & 63;
        const float* csp = g_cs + b * 512 + n * 8;
        float fb = bfbc;
#pragma unroll
        for (int j = 0; j < 8; ++j) fb = fmaf(csp[j], wf[j], fb);

        const size_t yo = (size_t)r * 768 + c;
        const size_t mo = (size_t)r * 256 + c;
        const int bitidx = (b * 8 + h) * 64 + n;

        // Q
        {
            float pre = fmaf(g_y[yo], sq, hq) + fb;
            float mem = fmaf(b0, qmem[mo], pre);
            bool  s   = mem > 1.0f;
            ob[O_QM + mo] = s ? (mem - 1.0f) : mem;
            unsigned bits = __ballot_sync(0xffffffffu, s);
            if (lane == 0) g_qbits[bitidx] = bits;
        }
        // K
        {
            float pre = fmaf(g_y[yo + 256], sk, hk) + fb;
            float mem = fmaf(b1, kmem[mo], pre);
            bool  s   = mem > 1.0f;
            ob[O_KM + mo] = s ? (mem - 1.0f) : mem;
            unsigned bits = __ballot_sync(0xffffffffu, s);
            if (lane == 0) g_kbits[bitidx] = bits;
        }
        // V
        {
            float pre = fmaf(g_y[yo + 512], sv, hv) + fb;
            float mem = fmaf(b2, vmem[mo], pre);
            bool  s   = mem > 1.0f;
            ob[O_VM + mo] = s ? (mem - 1.0f) : mem;
            unsigned bits = __ballot_sync(0xffffffffu, s);
            if (lane == 0) g_vbits[bitidx] = bits;
        }
    }
}

// ---------------- attention: gate -> cell LIF (zero reset) -> attn@v -> attn LIF --
__global__ __launch_bounds__(64) void k_attn(
    const float* __restrict__ cellmem, const float* __restrict__ attnmem,
    const int* __restrict__ mask, const float* __restrict__ betas,
    float* __restrict__ ob)
{
    const int bh = blockIdx.x;          // 0..8191 = b*8+h
    const int b = bh >> 3, h = bh & 7, w = b & 63;
    const int n = threadIdx.x;          // 0..63

    __shared__ unsigned kb[64], vb[64];
    __shared__ unsigned long long vT[32];

    kb[n] = g_kbits[bh * 64 + n];
    vb[n] = g_vbits[bh * 64 + n];
    __syncthreads();
    if (n < 32) {
        unsigned long long t = 0ull;
#pragma unroll
        for (int m = 0; m < 64; ++m)
            t |= (unsigned long long)((vb[m] >> n) & 1u) << m;
        vT[n] = t;
    }
    const unsigned q = g_qbits[bh * 64 + n];
    const float b3 = betas[3], b4 = betas[4];

    const float4* bias4 = (const float4*)(g_bias + h * 4096 + n * 64);
    const int4*   mp4   = (const int4*)(mask + w * 4096 + n * 64);
    const float4* cp4   = (const float4*)(cellmem + ((size_t)bh * 64 + n) * 64);
    float4*       cn4   = (float4*)(ob + O_CELL + ((size_t)bh * 64 + n) * 64);

    __syncthreads();   // vT ready

    unsigned long long amask = 0ull;
#pragma unroll 4
    for (int mq = 0; mq < 16; ++mq) {
        float4 bv = bias4[mq];
        int4   mv = mp4[mq];
        float4 cv = cp4[mq];
        float4 co;
        {
            int m = mq * 4 + 0;
            float gate = fmaf((float)__popc(q & kb[m]), 0.125f, bv.x);
            if (mv.x != 0) gate = 0.0f;
            float mem = fmaf(b3, cv.x, gate);
            bool  s   = mem > 1.0f;
            co.x = s ? 0.0f : mem;
            amask |= (unsigned long long)(s ? 1 : 0) << m;
        }
        {
            int m = mq * 4 + 1;
            float gate = fmaf((float)__popc(q & kb[m]), 0.125f, bv.y);
            if (mv.y != 0) gate = 0.0f;
            float mem = fmaf(b3, cv.y, gate);
            bool  s   = mem > 1.0f;
            co.y = s ? 0.0f : mem;
            amask |= (unsigned long long)(s ? 1 : 0) << m;
        }
        {
            int m = mq * 4 + 2;
            float gate = fmaf((float)__popc(q & kb[m]), 0.125f, bv.z);
            if (mv.z != 0) gate = 0.0f;
            float mem = fmaf(b3, cv.z, gate);
            bool  s   = mem > 1.0f;
            co.z = s ? 0.0f : mem;
            amask |= (unsigned long long)(s ? 1 : 0) << m;
        }
        {
            int m = mq * 4 + 3;
            float gate = fmaf((float)__popc(q & kb[m]), 0.125f, bv.w);
            if (mv.w != 0) gate = 0.0f;
            float mem = fmaf(b3, cv.w, gate);
            bool  s   = mem > 1.0f;
            co.w = s ? 0.0f : mem;
            amask |= (unsigned long long)(s ? 1 : 0) << m;
        }
        cn4[mq] = co;
    }

    // out[b,h,n,d] = 0.25 * popcll(amask & vT[d]); then attn-LIF (thr 0.5, soft)
    const size_t arow = ((size_t)b * 64 + n) * 256 + h * 32;
    const float* ap  = attnmem + arow;
    float*       amp = ob + O_AM + arow;
    float*       o2  = g_out2 + arow;
#pragma unroll 8
    for (int d2 = 0; d2 < 32; ++d2) {
        float o   = (float)__popcll(amask & vT[d2]) * 0.25f;
        float mem = fmaf(b4, ap[d2], o);
        float s   = mem > 0.5f ? 1.0f : 0.0f;
        amp[d2] = mem - 0.5f * s;
        o2[d2]  = s;
    }
}

// ---------------- final epilogue: BN(o) + LIF -> out spikes + om ----------------
__global__ void k_out_epi(const float* __restrict__ outmem,
                          const float* __restrict__ betas,
                          float* __restrict__ ob)
{
    const size_t i = (size_t)blockIdx.x * 256 + threadIdx.x;  // 16777216 elems
    const int c = (int)(i & 255);
    float y   = fmaf(g_yo[i], g_scale_o[c], g_shift_o[c]);
    float mem = fmaf(betas[5], outmem[i], y);
    float s   = mem > 1.0f ? 1.0f : 0.0f;
    ob[i]        = s;
    ob[O_OM + i] = mem - s;
}

// ---------------- launch ----------------
extern "C" void kernel_launch(void* const* d_in, const int* in_sizes, int n_in,
                              void* d_out, int out_size)
{
    const float* x       = (const float*)d_in[0];
    const float* qmem    = (const float*)d_in[1];
    const float* kmem    = (const float*)d_in[2];
    const float* vmem    = (const float*)d_in[3];
    const float* cellmem = (const float*)d_in[4];
    const float* attnmem = (const float*)d_in[5];
    const float* outmem  = (const float*)d_in[6];
    const float* Wq  = (const float*)d_in[7];
    const float* gq  = (const float*)d_in[9];
    const float* btq = (const float*)d_in[10];
    const float* Wk  = (const float*)d_in[11];
    const float* gk  = (const float*)d_in[13];
    const float* btk = (const float*)d_in[14];
    const float* Wv  = (const float*)d_in[15];
    const float* gv  = (const float*)d_in[17];
    const float* btv = (const float*)d_in[18];
    const float* Wfb = (const float*)d_in[19];
    const float* bfb = (const float*)d_in[20];
    const float* Wo  = (const float*)d_in[21];
    const float* go  = (const float*)d_in[23];
    const float* bto = (const float*)d_in[24];
    const float* rel_table = (const float*)d_in[25];
    const float* betas     = (const float*)d_in[26];
    const int*   mask      = (const int*)d_in[27];
    const int*   rel_index = (const int*)d_in[28];
    float* ob = (float*)d_out;
    // Note: linear biases bq/bk/bv/bo cancel inside BatchNorm (and are zero);
    // bfb does not cancel and is applied in k_qkv_epi.

    k_cs  <<<1024, 512>>>(cellmem);
    k_bias<<<128, 256>>>(rel_table, rel_index);

    dim3 g1(512, 2);
    sgemm<<<g1, 256>>>(x, Wq, 0, 768, 0);
    sgemm<<<g1, 256>>>(x, Wk, 0, 768, 256);
    sgemm<<<g1, 256>>>(x, Wv, 0, 768, 512);

    k_stats_partial<<<256, 768>>>(0, 768);
    k_stats_final  <<<1, 256>>>(gq, btq, 0,   0);
    k_stats_final  <<<1, 256>>>(gk, btk, 256, 0);
    k_stats_final  <<<1, 256>>>(gv, btv, 512, 0);

    k_qkv_epi<<<4096, 256>>>(qmem, kmem, vmem, Wfb, bfb, betas, ob);
    k_attn   <<<8192, 64>>>(cellmem, attnmem, mask, betas, ob);

    sgemm<<<g1, 256>>>(nullptr, Wo, 1, 256, 0);
    k_stats_partial<<<256, 256>>>(1, 256);
    k_stats_final  <<<1, 256>>>(go, bto, 0, 1);

    k_out_epi<<<65536, 256>>>(outmem, betas, ob);
}